// round 14
// baseline (speedup 1.0000x reference)
#include <cuda_runtime.h>
#include <cuda_fp16.h>
#include <math.h>

typedef unsigned int       u32;
typedef unsigned long long u64;

#define T_TOK 4096
#define D_DIM 1024
#define I_DIM 4096
#define E_NUM 8
#define ECAP  4096            // padded per-expert slot capacity

// ---------------- scratch (device globals; no runtime allocation) ----------
__device__ __half g_h[(size_t)T_TOK * D_DIM];                       // A for GEMM1
__device__ __half g_w1t[(size_t)E_NUM * I_DIM * D_DIM];             // [E][I][D]
__device__ __half g_w2t[(size_t)E_NUM * D_DIM * I_DIM];             // [E][D][I]
__device__ __half g_mid[(size_t)E_NUM * ECAP * I_DIM];              // A for GEMM2 (padded)
__device__ float g_eout[(size_t)E_NUM * ECAP * D_DIM];              // padded
__device__ int   g_sel[T_TOK * 2];
__device__ float g_wgt[T_TOK * 2];
__device__ int   g_slot[T_TOK * 2];
__device__ int   g_tok_of_slot[E_NUM * ECAP];
__device__ int   g_counts[E_NUM];
__device__ int   g_cursor[E_NUM];

// ---------------- PTX helpers ------------------------------------------------
__device__ __forceinline__ u32 smem_u32(const void* p) {
    u32 a;
    asm("{ .reg .u64 t; cvta.to.shared.u64 t, %1; cvt.u32.u64 %0, t; }"
        : "=r"(a) : "l"(p));
    return a;
}

#define CPA16(d, s) \
    asm volatile("cp.async.cg.shared.global [%0], [%1], 16;" \
                 :: "r"(d), "l"(s) : "memory")
#define CPA_COMMIT() asm volatile("cp.async.commit_group;" ::: "memory")
#define CPA_WAIT1()  asm volatile("cp.async.wait_group 1;" ::: "memory")
#define CPA_WAIT0()  asm volatile("cp.async.wait_group 0;" ::: "memory")

#define LDSM4(r0, r1, r2, r3, a) \
    asm volatile("ldmatrix.sync.aligned.m8n8.x4.shared.b16 {%0,%1,%2,%3}, [%4];" \
                 : "=r"(r0), "=r"(r1), "=r"(r2), "=r"(r3) : "r"(a))

#define MMA16816(c, a, b0, b1) \
    asm volatile("mma.sync.aligned.m16n8k16.row.col.f32.f16.f16.f32 " \
                 "{%0,%1,%2,%3}, {%4,%5,%6,%7}, {%8,%9}, {%0,%1,%2,%3};" \
                 : "+f"((c)[0]), "+f"((c)[1]), "+f"((c)[2]), "+f"((c)[3]) \
                 : "r"((a)[0]), "r"((a)[1]), "r"((a)[2]), "r"((a)[3]), \
                   "r"(b0), "r"(b1))

__device__ __forceinline__ float gelu_exact(float x) {
    return 0.5f * x * (1.0f + erff(x * 0.70710678118654752f));
}

__device__ __forceinline__ u32 packh2(float x, float y) {
    __half2 p = __floats2half2_rn(x, y);
    return *(u32*)&p;
}

// ---------------- 0: init ---------------------------------------------------
__global__ void init_kernel() {
    int i = threadIdx.x;
    if (i < E_NUM) { g_counts[i] = 0; g_cursor[i] = 0; }
}

// ---------------- 1: gating + h->fp16 (fused, R11 version) -------------------
__global__ void gate_kernel(const float* __restrict__ h,
                            const float* __restrict__ gw) {
    const int t = blockIdx.x;
    const int tid = threadIdx.x;
    const int warp = tid >> 5, lane = tid & 31;
    __shared__ float row[D_DIM];
    __shared__ float lg[E_NUM];

    float4 v = ((const float4*)(h + (size_t)t * D_DIM))[tid];
    u32 p0 = packh2(v.x, v.y);
    u32 p1 = packh2(v.z, v.w);
    ((uint2*)g_h)[(size_t)t * (D_DIM / 4) + tid] = make_uint2(p0, p1);
    ((float4*)row)[tid] = v;
    __syncthreads();

    const float* gr = gw + (size_t)warp * D_DIM;
    float s = 0.f;
    for (int j = lane; j < D_DIM; j += 32) s += row[j] * gr[j];
    #pragma unroll
    for (int o = 16; o; o >>= 1) s += __shfl_xor_sync(0xffffffffu, s, o);
    if (lane == 0) lg[warp] = s;
    __syncthreads();
    if (tid == 0) {
        float m = lg[0];
        #pragma unroll
        for (int e = 1; e < E_NUM; e++) m = fmaxf(m, lg[e]);
        float p[E_NUM], den = 0.f;
        #pragma unroll
        for (int e = 0; e < E_NUM; e++) { p[e] = expf(lg[e] - m); den += p[e]; }
        float inv_den = 1.0f / den;
        #pragma unroll
        for (int e = 0; e < E_NUM; e++) p[e] *= inv_den;
        int i0 = 0;
        #pragma unroll
        for (int e = 1; e < E_NUM; e++) if (p[e] > p[i0]) i0 = e;
        int i1 = (i0 == 0) ? 1 : 0;
        #pragma unroll
        for (int e = 0; e < E_NUM; e++)
            if (e != i0 && e != i1 && p[e] > p[i1]) i1 = e;
        float w0 = p[i0], w1 = p[i1];
        float inv = 1.0f / (w0 + w1);
        g_sel[2 * t + 0] = i0; g_sel[2 * t + 1] = i1;
        g_wgt[2 * t + 0] = w0 * inv; g_wgt[2 * t + 1] = w1 * inv;
        atomicAdd(&g_counts[i0], 1);
        atomicAdd(&g_counts[i1], 1);
    }
}

// ---------------- 2: scatter (padded slots) + aux loss -----------------------
__global__ void scatter_kernel(float* aux_out) {
    int t = blockIdx.x * blockDim.x + threadIdx.x;
    if (t == 0 && aux_out) {
        float aux = 0.f;
        #pragma unroll
        for (int e = 0; e < E_NUM; e++) {
            float u = (float)g_counts[e] / (float)T_TOK - 1.0f / (float)E_NUM;
            aux += u * u;
        }
        *aux_out = aux / (float)E_NUM;
    }
    if (t >= T_TOK) return;
    #pragma unroll
    for (int k = 0; k < 2; k++) {
        int e = g_sel[2 * t + k];
        int pos = atomicAdd(&g_cursor[e], 1);
        int s = (e << 12) + pos;           // e * ECAP + pos
        g_tok_of_slot[s] = t;
        g_slot[2 * t + k] = s;
    }
}

// ---------------- 3: transpose + convert weights to fp16 --------------------
// W [E][KDIM][NDIM] fp32 -> [E][NDIM][KDIM] fp16
template <bool W1>
__global__ void tsplit_kernel(const float* __restrict__ W) {
    const int KDIM = W1 ? D_DIM : I_DIM;
    const int NDIM = W1 ? I_DIM : D_DIM;
    __shared__ float t[64][33];
    const int e = blockIdx.z;
    const int n0 = blockIdx.x * 32, k0 = blockIdx.y * 64;
    const int tx = threadIdx.x, ty = threadIdx.y;   // (32, 8)
    const float* Wp = W + (size_t)e * KDIM * NDIM + n0 + tx;
    #pragma unroll
    for (int j = 0; j < 8; j++)
        t[ty + 8 * j][tx] = Wp[(size_t)(k0 + ty + 8 * j) * NDIM];
    __syncthreads();
    u32* oh = (u32*)(W1 ? g_w1t : g_w2t);
    #pragma unroll
    for (int j = 0; j < 4; j++) {
        const int n = ty + 8 * j;
        float x0 = t[2 * tx][n], x1 = t[2 * tx + 1][n];
        size_t o = ((size_t)e * NDIM * KDIM + (size_t)(n0 + n) * KDIM + k0) / 2 + tx;
        oh[o] = packh2(x0, x1);
    }
}

// ---------------- 4/5: expert GEMMs via fp16 mma.sync (unchanged) ------------
// C = A_f16 * B_f16 (fp32 accum). Block tile 128x128x32, 8 warps (2m x 4n).
// 2 stages x 2 matrices x 128 rows x 80B; compile-time stage parity.
#define ROWB   80
#define MATB   (128 * ROWB)       // 10240
#define STAGEB (2 * MATB)         // 20480
#define GSMEM_BYTES (2 * STAGEB)  // 40960

template <int KD, int ND, bool FIRST>
__global__ void __launch_bounds__(256, 2)
mma_gemm_kernel(const float* __restrict__ bias) {
    const int e = blockIdx.z;
    const int cnt = g_counts[e];
    const int m0 = blockIdx.x * 128;
    if (m0 >= cnt) return;
    const int base = e << 12;            // e * ECAP
    const int n0 = blockIdx.y * 128;

    extern __shared__ char smem[];
    const u32 sb = smem_u32(smem);

    const int tid  = threadIdx.x;
    const int lane = tid & 31, wid = tid >> 5;

    // ---- loader mapping: thread -> (row 0..127, k-half 0/1) ----
    const int lrow = tid >> 1;
    const int lkh  = (tid & 1) * 16;
    int am = m0 + lrow; if (am >= cnt) am = cnt - 1;
    const __half* pa;
    if (FIRST) {
        int tok = g_tok_of_slot[base + am];
        pa = g_h + (size_t)tok * KD;
    } else {
        pa = g_mid + (size_t)(base + am) * KD;
    }
    const __half* pb =
        (FIRST ? g_w1t : g_w2t) + ((size_t)e * ND + n0 + lrow) * KD;
    const u32 doff = (u32)(lrow * ROWB + (tid & 1) * 32);

    float c[4][4][4];
    #pragma unroll
    for (int i = 0; i < 4; i++)
        #pragma unroll
        for (int f = 0; f < 4; f++)
            #pragma unroll
            for (int q = 0; q < 4; q++) c[i][f][q] = 0.f;

    const int wm = (wid & 1) * 64;
    const int wn = (wid >> 1) * 32;
    const int l15 = lane & 15;
    const int lk16 = (lane >> 4) * 16;

    const int NK = KD / 32;

    // prologue: stage 0
    {
        const __half* s0 = pa + lkh;
        const __half* s1 = pb + lkh;
        u32 d = sb + doff;
        CPA16(d,        s0); CPA16(d + 16,        s0 + 8);
        CPA16(d + MATB, s1); CPA16(d + MATB + 16, s1 + 8);
    }
    CPA_COMMIT();

    #pragma unroll 1
    for (int kc = 0; kc < NK; kc++) {
        if (kc + 1 < NK) {
            const int kt = (kc + 1) * 32;
            const __half* s0 = pa + kt + lkh;
            const __half* s1 = pb + kt + lkh;
            u32 d = sb + ((kc + 1) & 1) * STAGEB + doff;
            CPA16(d,        s0); CPA16(d + 16,        s0 + 8);
            CPA16(d + MATB, s1); CPA16(d + MATB + 16, s1 + 8);
            CPA_COMMIT();
            CPA_WAIT1();
        } else {
            CPA_COMMIT();
            CPA_WAIT0();
        }
        __syncthreads();

        const u32 stb = sb + (kc & 1) * STAGEB;
        const u32 Am = stb, Bm = stb + MATB;

        #pragma unroll
        for (int s = 0; s < 2; s++) {
            const u32 koff = (u32)(s * 32 + lk16);

            u32 bh[8];
            #pragma unroll
            for (int j = 0; j < 2; j++) {
                u32 rb = (u32)((wn + j * 16 + l15) * ROWB) + koff;
                LDSM4(bh[j*4+0], bh[j*4+1], bh[j*4+2], bh[j*4+3], Bm + rb);
            }
            u32 ah[4][4];
            #pragma unroll
            for (int i = 0; i < 4; i++) {
                u32 ra = (u32)((wm + i * 16 + l15) * ROWB) + koff;
                LDSM4(ah[i][0], ah[i][1], ah[i][2], ah[i][3], Am + ra);
            }
            #pragma unroll
            for (int i = 0; i < 4; i++)
                #pragma unroll
                for (int f = 0; f < 4; f++) {
                    int j = f >> 1, r = f & 1;
                    MMA16816(c[i][f], ah[i], bh[j*4 + r], bh[j*4 + r + 2]);
                }
        }
        __syncthreads();
    }

    // ---- epilogue ----
    #pragma unroll
    for (int f = 0; f < 4; f++) {
        const int ncol = n0 + wn + f * 8 + (lane & 3) * 2;
        const float bz0 = bias[(size_t)e * ND + ncol];
        const float bz1 = bias[(size_t)e * ND + ncol + 1];
        #pragma unroll
        for (int i = 0; i < 4; i++) {
            const int mr0 = m0 + wm + i * 16 + (lane >> 2);
            #pragma unroll
            for (int half = 0; half < 2; half++) {
                const int m = mr0 + half * 8;
                if (m >= cnt) continue;
                float v0 = c[i][f][half * 2 + 0] + bz0;
                float v1 = c[i][f][half * 2 + 1] + bz1;
                const size_t off = (size_t)(base + m) * ND + ncol;
                if (FIRST) {
                    float y0 = gelu_exact(v0), y1 = gelu_exact(v1);
                    *(u32*)(g_mid + off) = packh2(y0, y1);
                } else {
                    *(float2*)(g_eout + off) = make_float2(v0, v1);
                }
            }
        }
    }
}

// ---------------- 6: combine + residual + LayerNorm -------------------------
__device__ __forceinline__ float blockReduceSum256(float v) {
    __shared__ float sm[8];
    #pragma unroll
    for (int o = 16; o; o >>= 1) v += __shfl_xor_sync(0xffffffffu, v, o);
    if ((threadIdx.x & 31) == 0) sm[threadIdx.x >> 5] = v;
    __syncthreads();
    float r = sm[threadIdx.x & 7];
    #pragma unroll
    for (int o = 4; o; o >>= 1) r += __shfl_xor_sync(0xffffffffu, r, o);
    __syncthreads();
    return r;
}

__global__ void combine_ln_kernel(const float* __restrict__ h,
                                  const float* __restrict__ mask,
                                  const float* __restrict__ gamma,
                                  const float* __restrict__ beta,
                                  float* __restrict__ out) {
    const int t = blockIdx.x;
    const float mk = mask[t];
    const int s0 = g_slot[2 * t + 0], s1 = g_slot[2 * t + 1];
    const float w0 = g_wgt[2 * t + 0], w1 = g_wgt[2 * t + 1];
    const float* e0 = g_eout + (size_t)s0 * D_DIM;
    const float* e1 = g_eout + (size_t)s1 * D_DIM;
    const float* hr = h + (size_t)t * D_DIM;

    float y[4];
    float s = 0.f;
    #pragma unroll
    for (int j = 0; j < 4; j++) {
        int d = threadIdx.x + j * 256;
        y[j] = hr[d] + mk * (w0 * e0[d] + w1 * e1[d]);
        s += y[j];
    }
    float mean = blockReduceSum256(s) * (1.0f / D_DIM);
    float vs = 0.f;
    #pragma unroll
    for (int j = 0; j < 4; j++) { float cdev = y[j] - mean; vs += cdev * cdev; }
    float var = blockReduceSum256(vs) * (1.0f / D_DIM);
    float rs = rsqrtf(var + 1e-5f);
    #pragma unroll
    for (int j = 0; j < 4; j++) {
        int d = threadIdx.x + j * 256;
        out[(size_t)t * D_DIM + d] = (y[j] - mean) * rs * gamma[d] + beta[d];
    }
}

// ---------------- launch -----------------------------------------------------
// Serial launch order chosen so ncu's "-s 5 -c 1" capture window lands on
// mma_gemm_kernel<...,true> (launch #6): init, tsplit1, tsplit2, gate,
// scatter, GEMM1, GEMM2, combine.
extern "C" void kernel_launch(void* const* d_in, const int* in_sizes, int n_in,
                              void* d_out, int out_size) {
    const float* h     = (const float*)d_in[0];
    const float* mask  = (const float*)d_in[1];
    const float* gw    = (const float*)d_in[2];
    const float* w1    = (const float*)d_in[3];
    const float* b1    = (const float*)d_in[4];
    const float* w2    = (const float*)d_in[5];
    const float* b2    = (const float*)d_in[6];
    const float* gamma = (const float*)d_in[7];
    const float* beta  = (const float*)d_in[8];
    float* out = (float*)d_out;

    float* aux_ptr = (out_size > T_TOK * D_DIM) ? (out + (size_t)T_TOK * D_DIM)
                                                : nullptr;

    static bool s_init = false;
    if (!s_init) {
        s_init = true;
        cudaFuncSetAttribute(mma_gemm_kernel<D_DIM, I_DIM, true>,
                             cudaFuncAttributeMaxDynamicSharedMemorySize, GSMEM_BYTES);
        cudaFuncSetAttribute(mma_gemm_kernel<I_DIM, D_DIM, false>,
                             cudaFuncAttributeMaxDynamicSharedMemorySize, GSMEM_BYTES);
    }

    init_kernel<<<1, 32>>>();                                            // 1
    { dim3 g(I_DIM / 32, D_DIM / 64, E_NUM);
      tsplit_kernel<true><<<g, dim3(32, 8)>>>(w1); }                     // 2
    { dim3 g(D_DIM / 32, I_DIM / 64, E_NUM);
      tsplit_kernel<false><<<g, dim3(32, 8)>>>(w2); }                    // 3
    gate_kernel<<<T_TOK, 256>>>(h, gw);                                  // 4
    scatter_kernel<<<(T_TOK + 255) / 256, 256>>>(aux_ptr);               // 5

    { dim3 g(T_TOK / 128, I_DIM / 128, E_NUM);                           // 6
      mma_gemm_kernel<D_DIM, I_DIM, true><<<g, 256, GSMEM_BYTES>>>(b1); }
    { dim3 g(T_TOK / 128, D_DIM / 128, E_NUM);                           // 7
      mma_gemm_kernel<I_DIM, D_DIM, false><<<g, 256, GSMEM_BYTES>>>(b2); }

    combine_ln_kernel<<<T_TOK, 256>>>(h, mask, gamma, beta, out);        // 8
}

// round 15
// speedup vs baseline: 1.1478x; 1.1478x over previous
#include <cuda_runtime.h>
#include <cuda_fp16.h>
#include <math.h>

typedef unsigned int       u32;
typedef unsigned long long u64;

#define T_TOK 4096
#define D_DIM 1024
#define I_DIM 4096
#define E_NUM 8
#define ECAP  4096            // padded per-expert slot capacity

// ---------------- scratch (device globals; no runtime allocation) ----------
__device__ __half g_h[(size_t)T_TOK * D_DIM];                       // A for GEMM1
__device__ __half g_w1t[(size_t)E_NUM * I_DIM * D_DIM];             // [E][I][D]
__device__ __half g_w2t[(size_t)E_NUM * D_DIM * I_DIM];             // [E][D][I]
__device__ __half g_mid[(size_t)E_NUM * ECAP * I_DIM];              // A for GEMM2 (padded)
__device__ float g_eout[(size_t)E_NUM * ECAP * D_DIM];              // padded
__device__ int   g_sel[T_TOK * 2];
__device__ float g_wgt[T_TOK * 2];
__device__ int   g_slot[T_TOK * 2];
__device__ int   g_tok_of_slot[E_NUM * ECAP];
__device__ int   g_counts[E_NUM];
__device__ int   g_cursor[E_NUM];

// ---------------- PTX helpers ------------------------------------------------
__device__ __forceinline__ u32 smem_u32(const void* p) {
    u32 a;
    asm("{ .reg .u64 t; cvta.to.shared.u64 t, %1; cvt.u32.u64 %0, t; }"
        : "=r"(a) : "l"(p));
    return a;
}

#define CPA16(d, s) \
    asm volatile("cp.async.cg.shared.global [%0], [%1], 16;" \
                 :: "r"(d), "l"(s) : "memory")
#define CPA_COMMIT() asm volatile("cp.async.commit_group;" ::: "memory")
#define CPA_WAIT2()  asm volatile("cp.async.wait_group 2;" ::: "memory")

#define LDSM4(r0, r1, r2, r3, a) \
    asm volatile("ldmatrix.sync.aligned.m8n8.x4.shared.b16 {%0,%1,%2,%3}, [%4];" \
                 : "=r"(r0), "=r"(r1), "=r"(r2), "=r"(r3) : "r"(a))

#define MMA16816(c, a, b0, b1) \
    asm volatile("mma.sync.aligned.m16n8k16.row.col.f32.f16.f16.f32 " \
                 "{%0,%1,%2,%3}, {%4,%5,%6,%7}, {%8,%9}, {%0,%1,%2,%3};" \
                 : "+f"((c)[0]), "+f"((c)[1]), "+f"((c)[2]), "+f"((c)[3]) \
                 : "r"((a)[0]), "r"((a)[1]), "r"((a)[2]), "r"((a)[3]), \
                   "r"(b0), "r"(b1))

__device__ __forceinline__ float gelu_exact(float x) {
    return 0.5f * x * (1.0f + erff(x * 0.70710678118654752f));
}

__device__ __forceinline__ u32 packh2(float x, float y) {
    __half2 p = __floats2half2_rn(x, y);
    return *(u32*)&p;
}

// ---------------- 0: init ---------------------------------------------------
__global__ void init_kernel() {
    int i = threadIdx.x;
    if (i < E_NUM) { g_counts[i] = 0; g_cursor[i] = 0; }
}

// ---------------- 1: gating + h->fp16 (fused) --------------------------------
__global__ void gate_kernel(const float* __restrict__ h,
                            const float* __restrict__ gw) {
    const int t = blockIdx.x;
    const int tid = threadIdx.x;
    const int warp = tid >> 5, lane = tid & 31;
    __shared__ float row[D_DIM];
    __shared__ float lg[E_NUM];

    float4 v = ((const float4*)(h + (size_t)t * D_DIM))[tid];
    u32 p0 = packh2(v.x, v.y);
    u32 p1 = packh2(v.z, v.w);
    ((uint2*)g_h)[(size_t)t * (D_DIM / 4) + tid] = make_uint2(p0, p1);
    ((float4*)row)[tid] = v;
    __syncthreads();

    const float* gr = gw + (size_t)warp * D_DIM;
    float s = 0.f;
    for (int j = lane; j < D_DIM; j += 32) s += row[j] * gr[j];
    #pragma unroll
    for (int o = 16; o; o >>= 1) s += __shfl_xor_sync(0xffffffffu, s, o);
    if (lane == 0) lg[warp] = s;
    __syncthreads();
    if (tid == 0) {
        float m = lg[0];
        #pragma unroll
        for (int e = 1; e < E_NUM; e++) m = fmaxf(m, lg[e]);
        float p[E_NUM], den = 0.f;
        #pragma unroll
        for (int e = 0; e < E_NUM; e++) { p[e] = expf(lg[e] - m); den += p[e]; }
        float inv_den = 1.0f / den;
        #pragma unroll
        for (int e = 0; e < E_NUM; e++) p[e] *= inv_den;
        int i0 = 0;
        #pragma unroll
        for (int e = 1; e < E_NUM; e++) if (p[e] > p[i0]) i0 = e;
        int i1 = (i0 == 0) ? 1 : 0;
        #pragma unroll
        for (int e = 0; e < E_NUM; e++)
            if (e != i0 && e != i1 && p[e] > p[i1]) i1 = e;
        float w0 = p[i0], w1 = p[i1];
        float inv = 1.0f / (w0 + w1);
        g_sel[2 * t + 0] = i0; g_sel[2 * t + 1] = i1;
        g_wgt[2 * t + 0] = w0 * inv; g_wgt[2 * t + 1] = w1 * inv;
        atomicAdd(&g_counts[i0], 1);
        atomicAdd(&g_counts[i1], 1);
    }
}

// ---------------- 2: scatter (padded slots) + aux loss -----------------------
__global__ void scatter_kernel(float* aux_out) {
    int t = blockIdx.x * blockDim.x + threadIdx.x;
    if (t == 0 && aux_out) {
        float aux = 0.f;
        #pragma unroll
        for (int e = 0; e < E_NUM; e++) {
            float u = (float)g_counts[e] / (float)T_TOK - 1.0f / (float)E_NUM;
            aux += u * u;
        }
        *aux_out = aux / (float)E_NUM;
    }
    if (t >= T_TOK) return;
    #pragma unroll
    for (int k = 0; k < 2; k++) {
        int e = g_sel[2 * t + k];
        int pos = atomicAdd(&g_cursor[e], 1);
        int s = (e << 12) + pos;           // e * ECAP + pos
        g_tok_of_slot[s] = t;
        g_slot[2 * t + k] = s;
    }
}

// ---------------- 3: transpose + convert weights to fp16 --------------------
// W [E][KDIM][NDIM] fp32 -> [E][NDIM][KDIM] fp16
template <bool W1>
__global__ void tsplit_kernel(const float* __restrict__ W) {
    const int KDIM = W1 ? D_DIM : I_DIM;
    const int NDIM = W1 ? I_DIM : D_DIM;
    __shared__ float t[64][33];
    const int e = blockIdx.z;
    const int n0 = blockIdx.x * 32, k0 = blockIdx.y * 64;
    const int tx = threadIdx.x, ty = threadIdx.y;   // (32, 8)
    const float* Wp = W + (size_t)e * KDIM * NDIM + n0 + tx;
    #pragma unroll
    for (int j = 0; j < 8; j++)
        t[ty + 8 * j][tx] = Wp[(size_t)(k0 + ty + 8 * j) * NDIM];
    __syncthreads();
    u32* oh = (u32*)(W1 ? g_w1t : g_w2t);
    #pragma unroll
    for (int j = 0; j < 4; j++) {
        const int n = ty + 8 * j;
        float x0 = t[2 * tx][n], x1 = t[2 * tx + 1][n];
        size_t o = ((size_t)e * NDIM * KDIM + (size_t)(n0 + n) * KDIM + k0) / 2 + tx;
        oh[o] = packh2(x0, x1);
    }
}

// ---------------- 4/5: expert GEMMs via fp16 mma.sync ------------------------
// C = A_f16 * B_f16 (fp32 accum). Block tile 128x128x32, 8 warps (2m x 4n).
// 4-stage cp.async pipeline, ONE barrier per chunk, compile-time stage idx
// via #pragma unroll 4 (NK = 32 or 128, both divisible by 4).
// Order per chunk: wait_group 2 -> barrier -> prefetch(kc+3) -> compute(kc).
// Prefetch-after-barrier makes the single barrier cover the WAR hazard on
// stage (kc+3)&3 == (kc-1)&3. An unconditional empty commit per iteration
// keeps wait_group counting exact through the tail.
#define ROWB   80
#define MATB   (128 * ROWB)       // 10240
#define STAGEB (2 * MATB)         // 20480
#define NSTAGE 4
#define GSMEM_BYTES (NSTAGE * STAGEB)  // 81920

template <int KD, int ND, bool FIRST>
__global__ void __launch_bounds__(256, 2)
mma_gemm_kernel(const float* __restrict__ bias) {
    const int e = blockIdx.z;
    const int cnt = g_counts[e];
    const int m0 = blockIdx.x * 128;
    if (m0 >= cnt) return;
    const int base = e << 12;            // e * ECAP
    const int n0 = blockIdx.y * 128;

    extern __shared__ char smem[];
    const u32 sb = smem_u32(smem);

    const int tid  = threadIdx.x;
    const int lane = tid & 31, wid = tid >> 5;

    // ---- loader mapping: thread -> (row 0..127, k-half 0/1) ----
    const int lrow = tid >> 1;
    const int lkh  = (tid & 1) * 16;
    int am = m0 + lrow; if (am >= cnt) am = cnt - 1;
    const __half* pa;
    if (FIRST) {
        int tok = g_tok_of_slot[base + am];
        pa = g_h + (size_t)tok * KD;
    } else {
        pa = g_mid + (size_t)(base + am) * KD;
    }
    const __half* pb =
        (FIRST ? g_w1t : g_w2t) + ((size_t)e * ND + n0 + lrow) * KD;
    const u32 doff = (u32)(lrow * ROWB + (tid & 1) * 32);

    float c[4][4][4];
    #pragma unroll
    for (int i = 0; i < 4; i++)
        #pragma unroll
        for (int f = 0; f < 4; f++)
            #pragma unroll
            for (int q = 0; q < 4; q++) c[i][f][q] = 0.f;

    const int wm = (wid & 1) * 64;
    const int wn = (wid >> 1) * 32;
    const int l15 = lane & 15;
    const int lk16 = (lane >> 4) * 16;

    const int NK = KD / 32;

    // prologue: stages 0, 1, 2
    #pragma unroll
    for (int st = 0; st < 3; st++) {
        const __half* s0 = pa + st * 32 + lkh;
        const __half* s1 = pb + st * 32 + lkh;
        u32 d = sb + st * STAGEB + doff;
        CPA16(d,        s0); CPA16(d + 16,        s0 + 8);
        CPA16(d + MATB, s1); CPA16(d + MATB + 16, s1 + 8);
        CPA_COMMIT();
    }

    #pragma unroll 4
    for (int kc = 0; kc < NK; kc++) {
        CPA_WAIT2();            // group kc complete (kc+1, kc+2 may be in flight)
        __syncthreads();        // all warps done reading stage (kc-1)&3

        if (kc + 3 < NK) {      // prefetch chunk kc+3 into stage (kc+3)&3
            const int kt = (kc + 3) * 32;
            const __half* s0 = pa + kt + lkh;
            const __half* s1 = pb + kt + lkh;
            u32 d = sb + ((kc + 3) & 3) * STAGEB + doff;
            CPA16(d,        s0); CPA16(d + 16,        s0 + 8);
            CPA16(d + MATB, s1); CPA16(d + MATB + 16, s1 + 8);
        }
        CPA_COMMIT();           // unconditional: keeps group counting exact

        const u32 stb = sb + (kc & 3) * STAGEB;
        const u32 Am = stb, Bm = stb + MATB;

        #pragma unroll
        for (int s = 0; s < 2; s++) {
            const u32 koff = (u32)(s * 32 + lk16);

            u32 bh[8];
            #pragma unroll
            for (int j = 0; j < 2; j++) {
                u32 rb = (u32)((wn + j * 16 + l15) * ROWB) + koff;
                LDSM4(bh[j*4+0], bh[j*4+1], bh[j*4+2], bh[j*4+3], Bm + rb);
            }
            u32 ah[4][4];
            #pragma unroll
            for (int i = 0; i < 4; i++) {
                u32 ra = (u32)((wm + i * 16 + l15) * ROWB) + koff;
                LDSM4(ah[i][0], ah[i][1], ah[i][2], ah[i][3], Am + ra);
            }
            #pragma unroll
            for (int i = 0; i < 4; i++)
                #pragma unroll
                for (int f = 0; f < 4; f++) {
                    int j = f >> 1, r = f & 1;
                    MMA16816(c[i][f], ah[i], bh[j*4 + r], bh[j*4 + r + 2]);
                }
        }
    }

    // ---- epilogue ----
    #pragma unroll
    for (int f = 0; f < 4; f++) {
        const int ncol = n0 + wn + f * 8 + (lane & 3) * 2;
        const float bz0 = bias[(size_t)e * ND + ncol];
        const float bz1 = bias[(size_t)e * ND + ncol + 1];
        #pragma unroll
        for (int i = 0; i < 4; i++) {
            const int mr0 = m0 + wm + i * 16 + (lane >> 2);
            #pragma unroll
            for (int half = 0; half < 2; half++) {
                const int m = mr0 + half * 8;
                if (m >= cnt) continue;
                float v0 = c[i][f][half * 2 + 0] + bz0;
                float v1 = c[i][f][half * 2 + 1] + bz1;
                const size_t off = (size_t)(base + m) * ND + ncol;
                if (FIRST) {
                    float y0 = gelu_exact(v0), y1 = gelu_exact(v1);
                    *(u32*)(g_mid + off) = packh2(y0, y1);
                } else {
                    *(float2*)(g_eout + off) = make_float2(v0, v1);
                }
            }
        }
    }
}

// ---------------- 6: combine + residual + LayerNorm -------------------------
__device__ __forceinline__ float blockReduceSum256(float v) {
    __shared__ float sm[8];
    #pragma unroll
    for (int o = 16; o; o >>= 1) v += __shfl_xor_sync(0xffffffffu, v, o);
    if ((threadIdx.x & 31) == 0) sm[threadIdx.x >> 5] = v;
    __syncthreads();
    float r = sm[threadIdx.x & 7];
    #pragma unroll
    for (int o = 4; o; o >>= 1) r += __shfl_xor_sync(0xffffffffu, r, o);
    __syncthreads();
    return r;
}

__global__ void combine_ln_kernel(const float* __restrict__ h,
                                  const float* __restrict__ mask,
                                  const float* __restrict__ gamma,
                                  const float* __restrict__ beta,
                                  float* __restrict__ out) {
    const int t = blockIdx.x;
    const float mk = mask[t];
    const int s0 = g_slot[2 * t + 0], s1 = g_slot[2 * t + 1];
    const float w0 = g_wgt[2 * t + 0], w1 = g_wgt[2 * t + 1];
    const float* e0 = g_eout + (size_t)s0 * D_DIM;
    const float* e1 = g_eout + (size_t)s1 * D_DIM;
    const float* hr = h + (size_t)t * D_DIM;

    float y[4];
    float s = 0.f;
    #pragma unroll
    for (int j = 0; j < 4; j++) {
        int d = threadIdx.x + j * 256;
        y[j] = hr[d] + mk * (w0 * e0[d] + w1 * e1[d]);
        s += y[j];
    }
    float mean = blockReduceSum256(s) * (1.0f / D_DIM);
    float vs = 0.f;
    #pragma unroll
    for (int j = 0; j < 4; j++) { float cdev = y[j] - mean; vs += cdev * cdev; }
    float var = blockReduceSum256(vs) * (1.0f / D_DIM);
    float rs = rsqrtf(var + 1e-5f);
    #pragma unroll
    for (int j = 0; j < 4; j++) {
        int d = threadIdx.x + j * 256;
        out[(size_t)t * D_DIM + d] = (y[j] - mean) * rs * gamma[d] + beta[d];
    }
}

// ---------------- launch -----------------------------------------------------
extern "C" void kernel_launch(void* const* d_in, const int* in_sizes, int n_in,
                              void* d_out, int out_size) {
    const float* h     = (const float*)d_in[0];
    const float* mask  = (const float*)d_in[1];
    const float* gw    = (const float*)d_in[2];
    const float* w1    = (const float*)d_in[3];
    const float* b1    = (const float*)d_in[4];
    const float* w2    = (const float*)d_in[5];
    const float* b2    = (const float*)d_in[6];
    const float* gamma = (const float*)d_in[7];
    const float* beta  = (const float*)d_in[8];
    float* out = (float*)d_out;

    float* aux_ptr = (out_size > T_TOK * D_DIM) ? (out + (size_t)T_TOK * D_DIM)
                                                : nullptr;

    // one-time host-side setup (no device memory)
    static cudaStream_t s_side = nullptr;
    static cudaEvent_t ev_start, ev_w1, ev_w2;
    if (!s_side) {
        cudaStreamCreateWithFlags(&s_side, cudaStreamNonBlocking);
        cudaEventCreateWithFlags(&ev_start, cudaEventDisableTiming);
        cudaEventCreateWithFlags(&ev_w1, cudaEventDisableTiming);
        cudaEventCreateWithFlags(&ev_w2, cudaEventDisableTiming);
        cudaFuncSetAttribute(mma_gemm_kernel<D_DIM, I_DIM, true>,
                             cudaFuncAttributeMaxDynamicSharedMemorySize, GSMEM_BYTES);
        cudaFuncSetAttribute(mma_gemm_kernel<I_DIM, D_DIM, false>,
                             cudaFuncAttributeMaxDynamicSharedMemorySize, GSMEM_BYTES);
    }

    // fork side stream: weight conversions overlap routing chain + GEMM1 gaps
    cudaEventRecord(ev_start, 0);
    cudaStreamWaitEvent(s_side, ev_start, 0);
    { dim3 g(I_DIM / 32, D_DIM / 64, E_NUM);
      tsplit_kernel<true><<<g, dim3(32, 8), 0, s_side>>>(w1); }
    cudaEventRecord(ev_w1, s_side);
    { dim3 g(D_DIM / 32, I_DIM / 64, E_NUM);
      tsplit_kernel<false><<<g, dim3(32, 8), 0, s_side>>>(w2); }
    cudaEventRecord(ev_w2, s_side);

    // main stream: routing chain (prefix kernel eliminated via padded slots)
    init_kernel<<<1, 32>>>();
    gate_kernel<<<T_TOK, 256>>>(h, gw);
    scatter_kernel<<<(T_TOK + 255) / 256, 256>>>(aux_ptr);

    // GEMM1 needs w1t
    cudaStreamWaitEvent(0, ev_w1, 0);
    { dim3 g(T_TOK / 128, I_DIM / 128, E_NUM);
      mma_gemm_kernel<D_DIM, I_DIM, true><<<g, 256, GSMEM_BYTES>>>(b1); }

    // GEMM2 needs w2t
    cudaStreamWaitEvent(0, ev_w2, 0);
    { dim3 g(T_TOK / 128, D_DIM / 128, E_NUM);
      mma_gemm_kernel<I_DIM, D_DIM, false><<<g, 256, GSMEM_BYTES>>>(b2); }

    combine_ln_kernel<<<T_TOK, 256>>>(h, mask, gamma, beta, out);
}

// round 16
// speedup vs baseline: 1.1490x; 1.0011x over previous
#include <cuda_runtime.h>
#include <cuda_fp16.h>
#include <math.h>

typedef unsigned int       u32;
typedef unsigned long long u64;

#define T_TOK 4096
#define D_DIM 1024
#define I_DIM 4096
#define E_NUM 8
#define ECAP  4096            // padded per-expert slot capacity

// ---------------- scratch (device globals; no runtime allocation) ----------
__device__ __half g_h[(size_t)T_TOK * D_DIM];                       // A for GEMM1
__device__ __half g_w1t[(size_t)E_NUM * I_DIM * D_DIM];             // [E][I][D]
__device__ __half g_w2t[(size_t)E_NUM * D_DIM * I_DIM];             // [E][D][I]
__device__ __half g_mid[(size_t)E_NUM * ECAP * I_DIM];              // A for GEMM2 (padded)
__device__ float g_eout[(size_t)E_NUM * ECAP * D_DIM];              // padded
__device__ float g_wgt[T_TOK * 2];
__device__ int   g_slot[T_TOK * 2];
__device__ int   g_tok_of_slot[E_NUM * ECAP];
__device__ int   g_cursor[E_NUM];   // doubles as final per-expert count

// ---------------- PTX helpers ------------------------------------------------
__device__ __forceinline__ u32 smem_u32(const void* p) {
    u32 a;
    asm("{ .reg .u64 t; cvta.to.shared.u64 t, %1; cvt.u32.u64 %0, t; }"
        : "=r"(a) : "l"(p));
    return a;
}

#define CPA16(d, s) \
    asm volatile("cp.async.cg.shared.global [%0], [%1], 16;" \
                 :: "r"(d), "l"(s) : "memory")
#define CPA_COMMIT() asm volatile("cp.async.commit_group;" ::: "memory")
#define CPA_WAIT2()  asm volatile("cp.async.wait_group 2;" ::: "memory")

#define LDSM4(r0, r1, r2, r3, a) \
    asm volatile("ldmatrix.sync.aligned.m8n8.x4.shared.b16 {%0,%1,%2,%3}, [%4];" \
                 : "=r"(r0), "=r"(r1), "=r"(r2), "=r"(r3) : "r"(a))

#define MMA16816(c, a, b0, b1) \
    asm volatile("mma.sync.aligned.m16n8k16.row.col.f32.f16.f16.f32 " \
                 "{%0,%1,%2,%3}, {%4,%5,%6,%7}, {%8,%9}, {%0,%1,%2,%3};" \
                 : "+f"((c)[0]), "+f"((c)[1]), "+f"((c)[2]), "+f"((c)[3]) \
                 : "r"((a)[0]), "r"((a)[1]), "r"((a)[2]), "r"((a)[3]), \
                   "r"(b0), "r"(b1))

__device__ __forceinline__ float gelu_exact(float x) {
    return 0.5f * x * (1.0f + erff(x * 0.70710678118654752f));
}

__device__ __forceinline__ u32 packh2(float x, float y) {
    __half2 p = __floats2half2_rn(x, y);
    return *(u32*)&p;
}

// ---------------- 0: init ---------------------------------------------------
__global__ void init_kernel() {
    int i = threadIdx.x;
    if (i < E_NUM) g_cursor[i] = 0;
}

// ---------------- 1: gating + h->fp16 + scatter (fully fused) ----------------
__global__ void gate_kernel(const float* __restrict__ h,
                            const float* __restrict__ gw) {
    const int t = blockIdx.x;
    const int tid = threadIdx.x;
    const int warp = tid >> 5, lane = tid & 31;
    __shared__ float row[D_DIM];
    __shared__ float lg[E_NUM];

    float4 v = ((const float4*)(h + (size_t)t * D_DIM))[tid];
    u32 p0 = packh2(v.x, v.y);
    u32 p1 = packh2(v.z, v.w);
    ((uint2*)g_h)[(size_t)t * (D_DIM / 4) + tid] = make_uint2(p0, p1);
    ((float4*)row)[tid] = v;
    __syncthreads();

    const float* gr = gw + (size_t)warp * D_DIM;
    float s = 0.f;
    for (int j = lane; j < D_DIM; j += 32) s += row[j] * gr[j];
    #pragma unroll
    for (int o = 16; o; o >>= 1) s += __shfl_xor_sync(0xffffffffu, s, o);
    if (lane == 0) lg[warp] = s;
    __syncthreads();
    if (tid == 0) {
        float m = lg[0];
        #pragma unroll
        for (int e = 1; e < E_NUM; e++) m = fmaxf(m, lg[e]);
        float p[E_NUM], den = 0.f;
        #pragma unroll
        for (int e = 0; e < E_NUM; e++) { p[e] = expf(lg[e] - m); den += p[e]; }
        float inv_den = 1.0f / den;
        #pragma unroll
        for (int e = 0; e < E_NUM; e++) p[e] *= inv_den;
        int i0 = 0;
        #pragma unroll
        for (int e = 1; e < E_NUM; e++) if (p[e] > p[i0]) i0 = e;
        int i1 = (i0 == 0) ? 1 : 0;
        #pragma unroll
        for (int e = 0; e < E_NUM; e++)
            if (e != i0 && e != i1 && p[e] > p[i1]) i1 = e;
        float w0 = p[i0], w1 = p[i1];
        float inv = 1.0f / (w0 + w1);
        g_wgt[2 * t + 0] = w0 * inv; g_wgt[2 * t + 1] = w1 * inv;
        // fused scatter: claim padded slots directly
        int pos0 = atomicAdd(&g_cursor[i0], 1);
        int s0 = (i0 << 12) + pos0;
        g_tok_of_slot[s0] = t; g_slot[2 * t + 0] = s0;
        int pos1 = atomicAdd(&g_cursor[i1], 1);
        int s1 = (i1 << 12) + pos1;
        g_tok_of_slot[s1] = t; g_slot[2 * t + 1] = s1;
    }
}

// ---------------- 2: transpose + convert weights to fp16 --------------------
// W [E][KDIM][NDIM] fp32 -> [E][NDIM][KDIM] fp16
template <bool W1>
__global__ void tsplit_kernel(const float* __restrict__ W) {
    const int KDIM = W1 ? D_DIM : I_DIM;
    const int NDIM = W1 ? I_DIM : D_DIM;
    __shared__ float t[64][33];
    const int e = blockIdx.z;
    const int n0 = blockIdx.x * 32, k0 = blockIdx.y * 64;
    const int tx = threadIdx.x, ty = threadIdx.y;   // (32, 8)
    const float* Wp = W + (size_t)e * KDIM * NDIM + n0 + tx;
    #pragma unroll
    for (int j = 0; j < 8; j++)
        t[ty + 8 * j][tx] = Wp[(size_t)(k0 + ty + 8 * j) * NDIM];
    __syncthreads();
    u32* oh = (u32*)(W1 ? g_w1t : g_w2t);
    #pragma unroll
    for (int j = 0; j < 4; j++) {
        const int n = ty + 8 * j;
        float x0 = t[2 * tx][n], x1 = t[2 * tx + 1][n];
        size_t o = ((size_t)e * NDIM * KDIM + (size_t)(n0 + n) * KDIM + k0) / 2 + tx;
        oh[o] = packh2(x0, x1);
    }
}

// ---------------- 3/4: expert GEMMs via fp16 mma.sync (R15 config, unchanged)-
// C = A_f16 * B_f16 (fp32 accum). Block tile 128x128x32, 8 warps (2m x 4n).
// 4-stage cp.async pipeline, ONE barrier per chunk, compile-time stage idx.
#define ROWB   80
#define MATB   (128 * ROWB)       // 10240
#define STAGEB (2 * MATB)         // 20480
#define NSTAGE 4
#define GSMEM_BYTES (NSTAGE * STAGEB)  // 81920

template <int KD, int ND, bool FIRST>
__global__ void __launch_bounds__(256, 2)
mma_gemm_kernel(const float* __restrict__ bias) {
    const int e = blockIdx.z;
    const int cnt = g_cursor[e];
    const int m0 = blockIdx.x * 128;
    if (m0 >= cnt) return;
    const int base = e << 12;            // e * ECAP
    const int n0 = blockIdx.y * 128;

    extern __shared__ char smem[];
    const u32 sb = smem_u32(smem);

    const int tid  = threadIdx.x;
    const int lane = tid & 31, wid = tid >> 5;

    // ---- loader mapping: thread -> (row 0..127, k-half 0/1) ----
    const int lrow = tid >> 1;
    const int lkh  = (tid & 1) * 16;
    int am = m0 + lrow; if (am >= cnt) am = cnt - 1;
    const __half* pa;
    if (FIRST) {
        int tok = g_tok_of_slot[base + am];
        pa = g_h + (size_t)tok * KD;
    } else {
        pa = g_mid + (size_t)(base + am) * KD;
    }
    const __half* pb =
        (FIRST ? g_w1t : g_w2t) + ((size_t)e * ND + n0 + lrow) * KD;
    const u32 doff = (u32)(lrow * ROWB + (tid & 1) * 32);

    float c[4][4][4];
    #pragma unroll
    for (int i = 0; i < 4; i++)
        #pragma unroll
        for (int f = 0; f < 4; f++)
            #pragma unroll
            for (int q = 0; q < 4; q++) c[i][f][q] = 0.f;

    const int wm = (wid & 1) * 64;
    const int wn = (wid >> 1) * 32;
    const int l15 = lane & 15;
    const int lk16 = (lane >> 4) * 16;

    const int NK = KD / 32;

    // prologue: stages 0, 1, 2
    #pragma unroll
    for (int st = 0; st < 3; st++) {
        const __half* s0 = pa + st * 32 + lkh;
        const __half* s1 = pb + st * 32 + lkh;
        u32 d = sb + st * STAGEB + doff;
        CPA16(d,        s0); CPA16(d + 16,        s0 + 8);
        CPA16(d + MATB, s1); CPA16(d + MATB + 16, s1 + 8);
        CPA_COMMIT();
    }

    #pragma unroll 4
    for (int kc = 0; kc < NK; kc++) {
        CPA_WAIT2();            // group kc complete (kc+1, kc+2 may be in flight)
        __syncthreads();        // all warps done reading stage (kc-1)&3

        if (kc + 3 < NK) {      // prefetch chunk kc+3 into stage (kc+3)&3
            const int kt = (kc + 3) * 32;
            const __half* s0 = pa + kt + lkh;
            const __half* s1 = pb + kt + lkh;
            u32 d = sb + ((kc + 3) & 3) * STAGEB + doff;
            CPA16(d,        s0); CPA16(d + 16,        s0 + 8);
            CPA16(d + MATB, s1); CPA16(d + MATB + 16, s1 + 8);
        }
        CPA_COMMIT();           // unconditional: keeps group counting exact

        const u32 stb = sb + (kc & 3) * STAGEB;
        const u32 Am = stb, Bm = stb + MATB;

        #pragma unroll
        for (int s = 0; s < 2; s++) {
            const u32 koff = (u32)(s * 32 + lk16);

            u32 bh[8];
            #pragma unroll
            for (int j = 0; j < 2; j++) {
                u32 rb = (u32)((wn + j * 16 + l15) * ROWB) + koff;
                LDSM4(bh[j*4+0], bh[j*4+1], bh[j*4+2], bh[j*4+3], Bm + rb);
            }
            u32 ah[4][4];
            #pragma unroll
            for (int i = 0; i < 4; i++) {
                u32 ra = (u32)((wm + i * 16 + l15) * ROWB) + koff;
                LDSM4(ah[i][0], ah[i][1], ah[i][2], ah[i][3], Am + ra);
            }
            #pragma unroll
            for (int i = 0; i < 4; i++)
                #pragma unroll
                for (int f = 0; f < 4; f++) {
                    int j = f >> 1, r = f & 1;
                    MMA16816(c[i][f], ah[i], bh[j*4 + r], bh[j*4 + r + 2]);
                }
        }
    }

    // ---- epilogue ----
    #pragma unroll
    for (int f = 0; f < 4; f++) {
        const int ncol = n0 + wn + f * 8 + (lane & 3) * 2;
        const float bz0 = bias[(size_t)e * ND + ncol];
        const float bz1 = bias[(size_t)e * ND + ncol + 1];
        #pragma unroll
        for (int i = 0; i < 4; i++) {
            const int mr0 = m0 + wm + i * 16 + (lane >> 2);
            #pragma unroll
            for (int half = 0; half < 2; half++) {
                const int m = mr0 + half * 8;
                if (m >= cnt) continue;
                float v0 = c[i][f][half * 2 + 0] + bz0;
                float v1 = c[i][f][half * 2 + 1] + bz1;
                const size_t off = (size_t)(base + m) * ND + ncol;
                if (FIRST) {
                    float y0 = gelu_exact(v0), y1 = gelu_exact(v1);
                    *(u32*)(g_mid + off) = packh2(y0, y1);
                } else {
                    *(float2*)(g_eout + off) = make_float2(v0, v1);
                }
            }
        }
    }
}

// ---------------- 5: combine + residual + LayerNorm + aux loss ---------------
__device__ __forceinline__ float blockReduceSum256(float v) {
    __shared__ float sm[8];
    #pragma unroll
    for (int o = 16; o; o >>= 1) v += __shfl_xor_sync(0xffffffffu, v, o);
    if ((threadIdx.x & 31) == 0) sm[threadIdx.x >> 5] = v;
    __syncthreads();
    float r = sm[threadIdx.x & 7];
    #pragma unroll
    for (int o = 4; o; o >>= 1) r += __shfl_xor_sync(0xffffffffu, r, o);
    __syncthreads();
    return r;
}

__global__ void combine_ln_kernel(const float* __restrict__ h,
                                  const float* __restrict__ mask,
                                  const float* __restrict__ gamma,
                                  const float* __restrict__ beta,
                                  float* __restrict__ out,
                                  float* aux_out) {
    const int t = blockIdx.x;
    if (t == 0 && threadIdx.x == 0 && aux_out) {
        float aux = 0.f;
        #pragma unroll
        for (int e = 0; e < E_NUM; e++) {
            float u = (float)g_cursor[e] / (float)T_TOK - 1.0f / (float)E_NUM;
            aux += u * u;
        }
        *aux_out = aux / (float)E_NUM;
    }
    const float mk = mask[t];
    const int s0 = g_slot[2 * t + 0], s1 = g_slot[2 * t + 1];
    const float w0 = g_wgt[2 * t + 0], w1 = g_wgt[2 * t + 1];
    const float* e0 = g_eout + (size_t)s0 * D_DIM;
    const float* e1 = g_eout + (size_t)s1 * D_DIM;
    const float* hr = h + (size_t)t * D_DIM;

    float y[4];
    float s = 0.f;
    #pragma unroll
    for (int j = 0; j < 4; j++) {
        int d = threadIdx.x + j * 256;
        y[j] = hr[d] + mk * (w0 * e0[d] + w1 * e1[d]);
        s += y[j];
    }
    float mean = blockReduceSum256(s) * (1.0f / D_DIM);
    float vs = 0.f;
    #pragma unroll
    for (int j = 0; j < 4; j++) { float cdev = y[j] - mean; vs += cdev * cdev; }
    float var = blockReduceSum256(vs) * (1.0f / D_DIM);
    float rs = rsqrtf(var + 1e-5f);
    #pragma unroll
    for (int j = 0; j < 4; j++) {
        int d = threadIdx.x + j * 256;
        out[(size_t)t * D_DIM + d] = (y[j] - mean) * rs * gamma[d] + beta[d];
    }
}

// ---------------- launch -----------------------------------------------------
extern "C" void kernel_launch(void* const* d_in, const int* in_sizes, int n_in,
                              void* d_out, int out_size) {
    const float* h     = (const float*)d_in[0];
    const float* mask  = (const float*)d_in[1];
    const float* gw    = (const float*)d_in[2];
    const float* w1    = (const float*)d_in[3];
    const float* b1    = (const float*)d_in[4];
    const float* w2    = (const float*)d_in[5];
    const float* b2    = (const float*)d_in[6];
    const float* gamma = (const float*)d_in[7];
    const float* beta  = (const float*)d_in[8];
    float* out = (float*)d_out;

    float* aux_ptr = (out_size > T_TOK * D_DIM) ? (out + (size_t)T_TOK * D_DIM)
                                                : nullptr;

    // one-time host-side setup (no device memory)
    static cudaStream_t s_side = nullptr;
    static cudaEvent_t ev_start, ev_w1, ev_w2;
    if (!s_side) {
        cudaStreamCreateWithFlags(&s_side, cudaStreamNonBlocking);
        cudaEventCreateWithFlags(&ev_start, cudaEventDisableTiming);
        cudaEventCreateWithFlags(&ev_w1, cudaEventDisableTiming);
        cudaEventCreateWithFlags(&ev_w2, cudaEventDisableTiming);
        cudaFuncSetAttribute(mma_gemm_kernel<D_DIM, I_DIM, true>,
                             cudaFuncAttributeMaxDynamicSharedMemorySize, GSMEM_BYTES);
        cudaFuncSetAttribute(mma_gemm_kernel<I_DIM, D_DIM, false>,
                             cudaFuncAttributeMaxDynamicSharedMemorySize, GSMEM_BYTES);
    }

    // fork side stream: weight conversions overlap routing chain + GEMM1 gaps
    cudaEventRecord(ev_start, 0);
    cudaStreamWaitEvent(s_side, ev_start, 0);
    { dim3 g(I_DIM / 32, D_DIM / 64, E_NUM);
      tsplit_kernel<true><<<g, dim3(32, 8), 0, s_side>>>(w1); }
    cudaEventRecord(ev_w1, s_side);
    { dim3 g(D_DIM / 32, I_DIM / 64, E_NUM);
      tsplit_kernel<false><<<g, dim3(32, 8), 0, s_side>>>(w2); }
    cudaEventRecord(ev_w2, s_side);

    // main stream: routing chain (scatter fused into gate)
    init_kernel<<<1, 32>>>();
    gate_kernel<<<T_TOK, 256>>>(h, gw);

    // GEMM1 needs w1t
    cudaStreamWaitEvent(0, ev_w1, 0);
    { dim3 g(T_TOK / 128, I_DIM / 128, E_NUM);
      mma_gemm_kernel<D_DIM, I_DIM, true><<<g, 256, GSMEM_BYTES>>>(b1); }

    // GEMM2 needs w2t
    cudaStreamWaitEvent(0, ev_w2, 0);
    { dim3 g(T_TOK / 128, D_DIM / 128, E_NUM);
      mma_gemm_kernel<I_DIM, D_DIM, false><<<g, 256, GSMEM_BYTES>>>(b2); }

    combine_ln_kernel<<<T_TOK, 256>>>(h, mask, gamma, beta, out, aux_ptr);
}